// round 7
// baseline (speedup 1.0000x reference)
#include <cuda_runtime.h>
#include <cuda_bf16.h>
#include <math.h>

#define IN_F   4096
#define OUT_F  4096
#define NROWS  16384
#define RANK   409
#define RANKP  448                 // pad so KCAT = 71*64
#define KCAT   (IN_F + RANKP)      // 4544
#define N_LR   512                 // lowrank N padded (4 tiles of 128)
#define XB     683
#define NBLOCKS (683*683)
#define KSEL   46649

#define BM 256
#define BN 128
#define BK 64
// stage layout: Ah 32KB | Al 32KB | Bh 16KB | Bl 16KB
#define SA_H 0
#define SA_L 32768
#define SB_H 65536
#define SB_L 81920
#define STG  98304
#define NSTAGE 2
#define SMEM_GEMM (NSTAGE*STG)     // 196608
#define NTHREADS 512

// ============================================================================
// helpers
// ============================================================================
__device__ __forceinline__ unsigned smem_u32(const void* p) {
    unsigned a;
    asm("{ .reg .u64 t; cvta.to.shared.u64 t, %1; cvt.u32.u64 %0, t; }" : "=r"(a) : "l"(p));
    return a;
}
__device__ __forceinline__ void cpasync16(unsigned dst, const void* src) {
    asm volatile("cp.async.cg.shared.global [%0], [%1], 16;" :: "r"(dst), "l"(src));
}
#define CP_COMMIT() asm volatile("cp.async.commit_group;" ::: "memory")
#define CP_WAIT1()  asm volatile("cp.async.wait_group 1;" ::: "memory")

__device__ __forceinline__ uint4 ldsm4(unsigned a) {
    uint4 r;
    asm volatile("ldmatrix.sync.aligned.m8n8.x4.shared.b16 {%0,%1,%2,%3}, [%4];"
                 : "=r"(r.x), "=r"(r.y), "=r"(r.z), "=r"(r.w) : "r"(a));
    return r;
}
__device__ __forceinline__ void mma16816(float* c, uint4 a, unsigned b0, unsigned b1) {
    asm volatile("mma.sync.aligned.m16n8k16.row.col.f32.bf16.bf16.f32 "
                 "{%0,%1,%2,%3},{%4,%5,%6,%7},{%8,%9},{%0,%1,%2,%3};"
                 : "+f"(c[0]), "+f"(c[1]), "+f"(c[2]), "+f"(c[3])
                 : "r"(a.x), "r"(a.y), "r"(a.z), "r"(a.w), "r"(b0), "r"(b1));
}
__device__ __forceinline__ void split2(float f0, float f1, unsigned& h, unsigned& l) {
    __nv_bfloat16 h0 = __float2bfloat16_rn(f0);
    __nv_bfloat16 h1 = __float2bfloat16_rn(f1);
    float r0 = f0 - __bfloat162float(h0);
    float r1 = f1 - __bfloat162float(h1);
    __nv_bfloat162 hh; hh.x = h0; hh.y = h1;
    __nv_bfloat162 ll; ll.x = __float2bfloat16_rn(r0); ll.y = __float2bfloat16_rn(r1);
    h = *reinterpret_cast<unsigned*>(&hh);
    l = *reinterpret_cast<unsigned*>(&ll);
}

// ============================================================================
// Static device scratch (referenced ONLY from device code)
// ============================================================================
__device__ float         d_g[NROWS];
__device__ __nv_bfloat16 d_ah[(size_t)NROWS * KCAT];   // [g*x | t] hi
__device__ __nv_bfloat16 d_al[(size_t)NROWS * KCAT];   // [g*x | t] lo
__device__ __nv_bfloat16 d_xh[(size_t)NROWS * IN_F];   // x hi (lowrank A)
__device__ __nv_bfloat16 d_xl[(size_t)NROWS * IN_F];
__device__ __nv_bfloat16 d_bh[(size_t)OUT_F * KCAT];   // [maskW | lr2^T] hi
__device__ __nv_bfloat16 d_bl[(size_t)OUT_F * KCAT];
__device__ __nv_bfloat16 d_b1h[(size_t)N_LR * IN_F];   // lr1^T hi
__device__ __nv_bfloat16 d_b1l[(size_t)N_LR * IN_F];
__device__ unsigned int  d_keys[NBLOCKS];
__device__ unsigned int  d_hist1[65536];
__device__ unsigned int  d_hist2[65536];
__device__ unsigned char d_active[NBLOCKS];
__device__ int           d_tied[65536];
__device__ int           d_tiedCnt;
__device__ unsigned int  d_selB;
__device__ unsigned int  d_selK1;
__device__ unsigned int  d_tau;
__device__ int           d_selR;

// ============================================================================
// Mask pipeline (unchanged from passing baseline)
// ============================================================================
__global__ void zeroK() {
    int i = blockIdx.x * blockDim.x + threadIdx.x;
    if (i < 65536)       d_hist1[i] = 0u;
    else if (i < 131072) d_hist2[i - 65536] = 0u;
    if (i == 0) d_tiedCnt = 0;
}

__global__ void gateK(const float* __restrict__ x, const float* __restrict__ gw,
                      const float* __restrict__ gb) {
    int warp = (blockIdx.x * blockDim.x + threadIdx.x) >> 5;
    int lane = threadIdx.x & 31;
    if (warp >= NROWS) return;
    const float4* xr = (const float4*)(x + (size_t)warp * IN_F);
    const float4* wv = (const float4*)gw;
    float s = 0.f;
    #pragma unroll 4
    for (int i = lane; i < IN_F / 4; i += 32) {
        float4 a = xr[i], b = wv[i];
        s += a.x * b.x + a.y * b.y + a.z * b.z + a.w * b.w;
    }
    #pragma unroll
    for (int o = 16; o; o >>= 1) s += __shfl_xor_sync(0xffffffffu, s, o);
    if (lane == 0) {
        float z = s + gb[0];
        d_g[warp] = 1.f / (1.f + expf(-z));
    }
}

__global__ void pooledK(const float* __restrict__ W) {
    int b = blockIdx.x * blockDim.x + threadIdx.x;
    if (b >= NBLOCKS) return;
    int bi = b / XB, bj = b % XB;
    int r0 = bi * 6, c0 = bj * 6;
    int rn = min(r0 + 6, IN_F), cn = min(c0 + 6, OUT_F);
    float s = 0.f;
    for (int r = r0; r < rn; ++r)
        for (int c = c0; c < cn; ++c)
            s += fabsf(W[(size_t)c * IN_F + r]);
    float p = s / (float)((rn - r0) * (cn - c0));
    unsigned int u = __float_as_uint(p);
    u = (u & 0x80000000u) ? ~u : (u | 0x80000000u);
    d_keys[b] = u;
    atomicAdd(&d_hist1[u >> 16], 1u);
}

__global__ void selectK(int pass) {
    __shared__ unsigned int csum[256];
    __shared__ unsigned int bins[256];
    __shared__ int sChunk;
    __shared__ unsigned int sG;
    const unsigned int* hist = (pass == 1) ? d_hist1 : d_hist2;
    unsigned int k = (pass == 1) ? (unsigned int)KSEL : d_selK1;
    int tid = threadIdx.x;
    unsigned int s = 0;
    for (int i = 0; i < 256; i++) s += hist[tid * 256 + i];
    csum[tid] = s;
    __syncthreads();
    if (tid == 0) {
        unsigned int c = 0; int ch = 255;
        for (; ch > 0; --ch) { if (c + csum[ch] >= k) break; c += csum[ch]; }
        sChunk = ch; sG = c;
    }
    __syncthreads();
    bins[tid] = hist[sChunk * 256 + tid];
    __syncthreads();
    if (tid == 0) {
        unsigned int c = sG; int bb = 255;
        for (; bb > 0; --bb) { if (c + bins[bb] >= k) break; c += bins[bb]; }
        unsigned int bin = (unsigned int)(sChunk * 256 + bb);
        if (pass == 1) { d_selB = bin; d_selK1 = k - c; }
        else           { d_tau = (d_selB << 16) | bin; d_selR = (int)(k - c); }
    }
}

__global__ void hist2K() {
    int b = blockIdx.x * blockDim.x + threadIdx.x;
    if (b >= NBLOCKS) return;
    unsigned int key = d_keys[b];
    if ((key >> 16) == d_selB) atomicAdd(&d_hist2[key & 0xFFFFu], 1u);
}

__global__ void markK() {
    int b = blockIdx.x * blockDim.x + threadIdx.x;
    if (b >= NBLOCKS) return;
    unsigned int key = d_keys[b];
    unsigned int tau = d_tau;
    d_active[b] = (key > tau) ? (unsigned char)1 : (unsigned char)0;
    if (key == tau) {
        int p = atomicAdd(&d_tiedCnt, 1);
        if (p < 65536) d_tied[p] = b;
    }
}

__global__ void resolveK() {
    if (threadIdx.x != 0 || blockIdx.x != 0) return;
    int T = d_tiedCnt; if (T > 65536) T = 65536;
    int r = d_selR;
    if (r >= T) { for (int i = 0; i < T; i++) d_active[d_tied[i]] = 1; return; }
    for (int i = 0; i < r; i++) {
        int best = i;
        for (int j = i + 1; j < T; j++)
            if (d_tied[j] < d_tied[best]) best = j;
        int tmp = d_tied[i]; d_tied[i] = d_tied[best]; d_tied[best] = tmp;
        d_active[d_tied[i]] = 1;
    }
}

// ============================================================================
// build B = [maskW | lr2^T] -> bf16 hi/lo     (rows n: OUT_F, cols k: KCAT)
// ============================================================================
__global__ void buildBK(const float* __restrict__ W, const float* __restrict__ lr2) {
    int idx = blockIdx.x * blockDim.x + threadIdx.x;
    if (idx >= OUT_F * (KCAT / 4)) return;
    int n = idx / (KCAT / 4);
    int q = (idx - n * (KCAT / 4)) * 4;
    float v[4];
    if (q < IN_F) {
        float4 w = *(const float4*)(W + (size_t)n * IN_F + q);
        int nb = n / 6;
        v[0] = d_active[((q + 0) / 6) * XB + nb] ? w.x : 0.f;
        v[1] = d_active[((q + 1) / 6) * XB + nb] ? w.y : 0.f;
        v[2] = d_active[((q + 2) / 6) * XB + nb] ? w.z : 0.f;
        v[3] = d_active[((q + 3) / 6) * XB + nb] ? w.w : 0.f;
    } else {
        int r = q - IN_F;
        #pragma unroll
        for (int i = 0; i < 4; i++)
            v[i] = (r + i < RANK) ? lr2[(size_t)(r + i) * OUT_F + n] : 0.f;
    }
    unsigned h0, l0, h1, l1;
    split2(v[0], v[1], h0, l0);
    split2(v[2], v[3], h1, l1);
    *(uint2*)((char*)d_bh + ((size_t)n * KCAT + q) * 2) = make_uint2(h0, h1);
    *(uint2*)((char*)d_bl + ((size_t)n * KCAT + q) * 2) = make_uint2(l0, l1);
}

// B1 = lr1^T padded to N_LR rows -> bf16 hi/lo
__global__ void buildB1K(const float* __restrict__ lr1) {
    int idx = blockIdx.x * blockDim.x + threadIdx.x;
    if (idx >= N_LR * (IN_F / 4)) return;
    int n = idx / (IN_F / 4);
    int q = (idx - n * (IN_F / 4)) * 4;
    float v[4];
    #pragma unroll
    for (int i = 0; i < 4; i++)
        v[i] = (n < RANK) ? lr1[(size_t)(q + i) * RANK + n] : 0.f;
    unsigned h0, l0, h1, l1;
    split2(v[0], v[1], h0, l0);
    split2(v[2], v[3], h1, l1);
    *(uint2*)((char*)d_b1h + ((size_t)n * IN_F + q) * 2) = make_uint2(h0, h1);
    *(uint2*)((char*)d_b1l + ((size_t)n * IN_F + q) * 2) = make_uint2(l0, l1);
}

// fused: x -> (xh, xl) AND g*x -> (ah, al) cols 0..IN_F-1 (single read of x)
__global__ void splitXK(const float* __restrict__ x) {
    int idx = blockIdx.x * blockDim.x + threadIdx.x;
    if (idx >= NROWS * (IN_F / 4)) return;
    int e = idx * 4;
    int row = e >> 12;
    int col = e & 4095;
    float g = d_g[row];
    float4 v = ((const float4*)x)[idx];
    unsigned h0, l0, h1, l1;
    split2(v.x, v.y, h0, l0);
    split2(v.z, v.w, h1, l1);
    ((uint2*)d_xh)[idx] = make_uint2(h0, h1);
    ((uint2*)d_xl)[idx] = make_uint2(l0, l1);
    split2(g * v.x, g * v.y, h0, l0);
    split2(g * v.z, g * v.w, h1, l1);
    size_t o = (size_t)row * KCAT + col;
    *(uint2*)((char*)d_ah + o * 2) = make_uint2(h0, h1);
    *(uint2*)((char*)d_al + o * 2) = make_uint2(l0, l1);
}

// ============================================================================
// bf16x3 GEMM: CTA 256x128, 16 warps (4x4), warp tile 64x32, 2-stage cp.async.
// MAIN: A=[g*x|t] (lda=KCAT), B=[maskW|lr2^T], out = acc + g*bs + (1-g)*bl
// LR:   A=x (lda=IN_F), B=lr1^T, epilogue writes t=(1-g)*acc into d_ah/d_al
// ============================================================================
__device__ __forceinline__ void load_stage(unsigned sbase,
    const __nv_bfloat16* __restrict__ Ah, const __nv_bfloat16* __restrict__ Al,
    int lda, int m0,
    const __nv_bfloat16* __restrict__ Bh, const __nv_bfloat16* __restrict__ Bl,
    int ldb, int n0, int k0, int tid) {
    // A: 256 rows x 128B (hi+lo). 512 thr: row = tid>>1, half = tid&1 (64B each)
    {
        int row = tid >> 1, h = tid & 1;
        const __nv_bfloat16* a_h = Ah + (size_t)(m0 + row) * lda + k0 + h * 32;
        const __nv_bfloat16* a_l = Al + (size_t)(m0 + row) * lda + k0 + h * 32;
        unsigned drow = (unsigned)(row * 128);
        #pragma unroll
        for (int j = 0; j < 4; j++) {
            unsigned d = drow + (unsigned)((((h * 4 + j) ^ (row & 7)) * 16));
            cpasync16(sbase + SA_H + d, a_h + j * 8);
            cpasync16(sbase + SA_L + d, a_l + j * 8);
        }
    }
    // B: 128 rows x 128B (hi+lo). row = tid>>2, q = tid&3 (32B each)
    {
        int row = tid >> 2, q = tid & 3;
        const __nv_bfloat16* b_h = Bh + (size_t)(n0 + row) * ldb + k0 + q * 16;
        const __nv_bfloat16* b_l = Bl + (size_t)(n0 + row) * ldb + k0 + q * 16;
        unsigned drow = (unsigned)(row * 128);
        #pragma unroll
        for (int j = 0; j < 2; j++) {
            unsigned d = drow + (unsigned)((((q * 2 + j) ^ (row & 7)) * 16));
            cpasync16(sbase + SB_H + d, b_h + j * 8);
            cpasync16(sbase + SB_L + d, b_l + j * 8);
        }
    }
}

template<bool MAIN>
__global__ __launch_bounds__(NTHREADS, 1) void mmaK(
    const float* __restrict__ bsp, const float* __restrict__ blp,
    float* __restrict__ out) {
    extern __shared__ __align__(1024) char smem[];
    unsigned sb = smem_u32(smem);
    int tid = threadIdx.x;

    const __nv_bfloat16* Ah = MAIN ? d_ah : d_xh;
    const __nv_bfloat16* Al = MAIN ? d_al : d_xl;
    const __nv_bfloat16* Bh = MAIN ? d_bh : d_b1h;
    const __nv_bfloat16* Bl = MAIN ? d_bl : d_b1l;
    const int lda = MAIN ? KCAT : IN_F;
    const int ldb = MAIN ? KCAT : IN_F;
    const int nch = MAIN ? (KCAT / BK) : (IN_F / BK);
    const int pn  = MAIN ? (OUT_F / BN) : (N_LR / BN);

    // CTA raster: groups of 8 m-tiles for L2 reuse of B strips
    int pid = blockIdx.x;
    const int GM = 8;
    int grp = pid / (GM * pn);
    int mt  = grp * GM + (pid % GM);
    int nt  = (pid % (GM * pn)) / GM;
    int m0 = mt * BM, n0 = nt * BN;

    load_stage(sb + 0 * STG, Ah, Al, lda, m0, Bh, Bl, ldb, n0, 0, tid);
    CP_COMMIT();
    load_stage(sb + 1 * STG, Ah, Al, lda, m0, Bh, Bl, ldb, n0, BK, tid);
    CP_COMMIT();

    int wid = tid >> 5, lane = tid & 31;
    int wm = wid >> 2, wn = wid & 3;                         // 4 x 4 warps
    int arb = wm * 64 + (lane & 7) + ((lane >> 3) & 1) * 8;  // + mi*16
    int cA = lane >> 4;
    int br = wn * 32 + (lane & 7) + (lane >> 4) * 8;         // + g*16
    int cB = (lane >> 3) & 1;

    float acc[4][4][4];
    #pragma unroll
    for (int a = 0; a < 4; a++)
        #pragma unroll
        for (int b = 0; b < 4; b++)
            #pragma unroll
            for (int c = 0; c < 4; c++) acc[a][b][c] = 0.f;

    for (int ch = 0; ch < nch; ch++) {
        CP_WAIT1();
        __syncthreads();
        unsigned base = sb + (ch & 1) * STG;
        #pragma unroll
        for (int kk = 0; kk < 4; kk++) {
            uint4 fbh[2], fbl[2];
            #pragma unroll
            for (int g = 0; g < 2; g++) {
                int r = br + g * 16;
                unsigned off = (unsigned)(r * 128 + (((kk * 2 + cB) ^ (r & 7)) * 16));
                fbh[g] = ldsm4(base + SB_H + off);
                fbl[g] = ldsm4(base + SB_L + off);
            }
            #pragma unroll
            for (int mih = 0; mih < 2; mih++) {
                uint4 fah[2], fal[2];
                #pragma unroll
                for (int i = 0; i < 2; i++) {
                    int r = arb + (mih * 2 + i) * 16;
                    unsigned off = (unsigned)(r * 128 + (((kk * 2 + cA) ^ (r & 7)) * 16));
                    fah[i] = ldsm4(base + SA_H + off);
                    fal[i] = ldsm4(base + SA_L + off);
                }
                // product-major ordering to space accumulator RAW
                #pragma unroll
                for (int i = 0; i < 2; i++) {
                    int mi = mih * 2 + i;
                    #pragma unroll
                    for (int g = 0; g < 2; g++) {
                        mma16816(acc[mi][2 * g],     fah[i], fbh[g].x, fbh[g].y);
                        mma16816(acc[mi][2 * g + 1], fah[i], fbh[g].z, fbh[g].w);
                    }
                }
                #pragma unroll
                for (int i = 0; i < 2; i++) {
                    int mi = mih * 2 + i;
                    #pragma unroll
                    for (int g = 0; g < 2; g++) {
                        mma16816(acc[mi][2 * g],     fah[i], fbl[g].x, fbl[g].y);
                        mma16816(acc[mi][2 * g + 1], fah[i], fbl[g].z, fbl[g].w);
                    }
                }
                #pragma unroll
                for (int i = 0; i < 2; i++) {
                    int mi = mih * 2 + i;
                    #pragma unroll
                    for (int g = 0; g < 2; g++) {
                        mma16816(acc[mi][2 * g],     fal[i], fbh[g].x, fbh[g].y);
                        mma16816(acc[mi][2 * g + 1], fal[i], fbh[g].z, fbh[g].w);
                    }
                }
            }
        }
        __syncthreads();
        if (ch + 2 < nch) {
            load_stage(base, Ah, Al, lda, m0, Bh, Bl, ldb, n0, (ch + 2) * BK, tid);
        }
        CP_COMMIT();
    }

    // epilogue
    #pragma unroll
    for (int mi = 0; mi < 4; mi++) {
        #pragma unroll
        for (int r2 = 0; r2 < 2; r2++) {
            int m = m0 + wm * 64 + mi * 16 + (lane >> 2) + r2 * 8;
            float g = d_g[m];
            float og = 1.f - g;
            #pragma unroll
            for (int n8 = 0; n8 < 4; n8++) {
                int col = n0 + wn * 32 + n8 * 8 + (lane & 3) * 2;
                float a0 = acc[mi][n8][r2 * 2];
                float a1 = acc[mi][n8][r2 * 2 + 1];
                if (MAIN) {
                    float2 b1 = *(const float2*)(bsp + col);
                    float2 b2 = *(const float2*)(blp + col);
                    float2 o;
                    o.x = a0 + g * b1.x + og * b2.x;
                    o.y = a1 + g * b1.y + og * b2.y;
                    *(float2*)(out + (size_t)m * OUT_F + col) = o;
                } else {
                    if (col < RANKP) {
                        unsigned h, l;
                        split2(og * a0, og * a1, h, l);
                        size_t o = (size_t)m * KCAT + IN_F + col;
                        *(unsigned*)((char*)d_ah + o * 2) = h;
                        *(unsigned*)((char*)d_al + o * 2) = l;
                    }
                }
            }
        }
    }
}

// ============================================================================
// launch
// ============================================================================
extern "C" void kernel_launch(void* const* d_in, const int* in_sizes, int n_in,
                              void* d_out, int out_size) {
    const float* x      = (const float*)d_in[0];
    const float* gate_w = (const float*)d_in[1];
    const float* gate_b = (const float*)d_in[2];
    const float* weight = (const float*)d_in[3];
    const float* s_bias = (const float*)d_in[4];
    const float* lr1    = (const float*)d_in[5];
    const float* lr2    = (const float*)d_in[6];
    const float* l_bias = (const float*)d_in[7];
    float* out = (float*)d_out;

    cudaFuncSetAttribute(mmaK<false>, cudaFuncAttributeMaxDynamicSharedMemorySize, SMEM_GEMM);
    cudaFuncSetAttribute(mmaK<true>,  cudaFuncAttributeMaxDynamicSharedMemorySize, SMEM_GEMM);

    // launch index 3 = LR1 GEMM (ncu captures index 3)
    gateK<<<(NROWS * 32 + 255) / 256, 256>>>(x, gate_w, gate_b);          // 0
    splitXK<<<(NROWS * (IN_F / 4) + 255) / 256, 256>>>(x);                // 1
    buildB1K<<<(N_LR * (IN_F / 4) + 255) / 256, 256>>>(lr1);              // 2
    mmaK<false><<<(NROWS / BM) * (N_LR / BN), NTHREADS, SMEM_GEMM>>>(     // 3
        nullptr, nullptr, nullptr);
    zeroK<<<(131072 + 255) / 256, 256>>>();                               // 4
    pooledK<<<(NBLOCKS + 255) / 256, 256>>>(weight);                      // 5
    selectK<<<1, 256>>>(1);                                               // 6
    hist2K<<<(NBLOCKS + 255) / 256, 256>>>();                             // 7
    selectK<<<1, 256>>>(2);                                               // 8
    markK<<<(NBLOCKS + 255) / 256, 256>>>();                              // 9
    resolveK<<<1, 1>>>();                                                 // 10
    buildBK<<<(OUT_F * (KCAT / 4) + 255) / 256, 256>>>(weight, lr2);      // 11
    // main: out = [g*x | t] @ [maskW | lr2^T]^T + g*bs + (1-g)*bl
    mmaK<true><<<(NROWS / BM) * (OUT_F / BN), NTHREADS, SMEM_GEMM>>>(     // 12
        s_bias, l_bias, out);
}